// round 1
// baseline (speedup 1.0000x reference)
#include <cuda_runtime.h>

#define B_ 8
#define S_ 2048
#define E_ 4096
#define H_ 128

// Scratch (allocation-free rule: __device__ globals)
__device__ float g_q[B_ * S_ * H_];                 // 8 MB
__device__ float g_k[B_ * S_ * H_];                 // 8 MB
__device__ float g_v[B_ * S_ * H_];                 // 8 MB
__device__ float g_s[(size_t)B_ * S_ * S_];         // 134 MB (scores / probs)

// ---------------------------------------------------------------------------
// Kernel 1: projections. C[16384,128] = X[16384,4096] @ W[4096,128]
// blockIdx.z selects (Wq->g_q, Wk->g_k, Wv->g_v).
// BM=64, BN=128, BK=16; 256 threads; per-thread 8x4 micro-tile.
// ---------------------------------------------------------------------------
__global__ __launch_bounds__(256) void proj_kernel(
    const float* __restrict__ x,
    const float* __restrict__ Wq,
    const float* __restrict__ Wk,
    const float* __restrict__ Wv)
{
    __shared__ float As[16][64 + 4];   // transposed, padded (stride 68 -> 16B aligned)
    __shared__ float Bs[16][128];

    const float* W = (blockIdx.z == 0) ? Wq : (blockIdx.z == 1) ? Wk : Wv;
    float* C       = (blockIdx.z == 0) ? g_q : (blockIdx.z == 1) ? g_k : g_v;

    const int m0  = blockIdx.x * 64;
    const int tid = threadIdx.x;
    const int ty  = tid >> 5;   // 0..7  (row group of 8)
    const int tx  = tid & 31;   // 0..31 (col group of 4)

    float acc[8][4];
    #pragma unroll
    for (int i = 0; i < 8; i++)
        #pragma unroll
        for (int j = 0; j < 4; j++) acc[i][j] = 0.f;

    for (int k0 = 0; k0 < E_; k0 += 16) {
        #pragma unroll
        for (int i = 0; i < 4; i++) {          // A tile 64x16
            int lin = tid + i * 256;
            int r = lin >> 4, c = lin & 15;
            As[c][r] = x[(m0 + r) * E_ + k0 + c];
        }
        #pragma unroll
        for (int i = 0; i < 8; i++) {          // B tile 16x128
            int lin = tid + i * 256;
            int r = lin >> 7, c = lin & 127;
            Bs[r][c] = W[(k0 + r) * H_ + c];
        }
        __syncthreads();

        #pragma unroll
        for (int kk = 0; kk < 16; kk++) {
            float4 a0 = *(const float4*)(&As[kk][ty * 8]);
            float4 a1 = *(const float4*)(&As[kk][ty * 8 + 4]);
            float4 bv = *(const float4*)(&Bs[kk][tx * 4]);
            float a[8] = {a0.x, a0.y, a0.z, a0.w, a1.x, a1.y, a1.z, a1.w};
            float b[4] = {bv.x, bv.y, bv.z, bv.w};
            #pragma unroll
            for (int i = 0; i < 8; i++)
                #pragma unroll
                for (int j = 0; j < 4; j++)
                    acc[i][j] = fmaf(a[i], b[j], acc[i][j]);
        }
        __syncthreads();
    }

    #pragma unroll
    for (int i = 0; i < 8; i++) {
        float4 v = make_float4(acc[i][0], acc[i][1], acc[i][2], acc[i][3]);
        *(float4*)&C[(m0 + ty * 8 + i) * H_ + tx * 4] = v;
    }
}

// ---------------------------------------------------------------------------
// Kernel 2: scores. S[b] = q[b] @ k[b]^T * scale. 64x64 tiles, K=128.
// 256 threads, per-thread 4x4 micro-tile.
// ---------------------------------------------------------------------------
__global__ __launch_bounds__(256) void scores_kernel()
{
    __shared__ float Qs[16][64 + 4];
    __shared__ float Ks[16][64 + 4];

    const int b  = blockIdx.z;
    const int m0 = blockIdx.y * 64;
    const int n0 = blockIdx.x * 64;

    const float* q = g_q + b * S_ * H_;
    const float* k = g_k + b * S_ * H_;
    float* s = g_s + (size_t)b * S_ * S_;

    const int tid = threadIdx.x;
    const int ty  = tid >> 4;   // 0..15
    const int tx  = tid & 15;   // 0..15
    const float scale = 0.08838834764831845f;  // 1/sqrt(128)

    float acc[4][4];
    #pragma unroll
    for (int i = 0; i < 4; i++)
        #pragma unroll
        for (int j = 0; j < 4; j++) acc[i][j] = 0.f;

    for (int k0 = 0; k0 < H_; k0 += 16) {
        #pragma unroll
        for (int i = 0; i < 4; i++) {
            int lin = tid + i * 256;
            int r = lin >> 4, c = lin & 15;
            Qs[c][r] = q[(m0 + r) * H_ + k0 + c];
            Ks[c][r] = k[(n0 + r) * H_ + k0 + c];
        }
        __syncthreads();

        #pragma unroll
        for (int kk = 0; kk < 16; kk++) {
            float4 av = *(const float4*)(&Qs[kk][ty * 4]);
            float4 bv = *(const float4*)(&Ks[kk][tx * 4]);
            float a[4] = {av.x, av.y, av.z, av.w};
            float bb[4] = {bv.x, bv.y, bv.z, bv.w};
            #pragma unroll
            for (int i = 0; i < 4; i++)
                #pragma unroll
                for (int j = 0; j < 4; j++)
                    acc[i][j] = fmaf(a[i], bb[j], acc[i][j]);
        }
        __syncthreads();
    }

    #pragma unroll
    for (int i = 0; i < 4; i++) {
        float4 v = make_float4(acc[i][0] * scale, acc[i][1] * scale,
                               acc[i][2] * scale, acc[i][3] * scale);
        *(float4*)&s[(size_t)(m0 + ty * 4 + i) * S_ + n0 + tx * 4] = v;
    }
}

// ---------------------------------------------------------------------------
// Kernel 3: row softmax over 2048 cols; one block per row, row in registers.
// ---------------------------------------------------------------------------
__global__ __launch_bounds__(256) void softmax_kernel()
{
    __shared__ float red[8];
    float* p = g_s + (size_t)blockIdx.x * S_;
    const int tid  = threadIdx.x;
    const int lane = tid & 31;
    const int warp = tid >> 5;

    float4 v0 = ((const float4*)p)[tid * 2];
    float4 v1 = ((const float4*)p)[tid * 2 + 1];
    float v[8] = {v0.x, v0.y, v0.z, v0.w, v1.x, v1.y, v1.z, v1.w};

    // max reduce
    float m = v[0];
    #pragma unroll
    for (int i = 1; i < 8; i++) m = fmaxf(m, v[i]);
    #pragma unroll
    for (int o = 16; o > 0; o >>= 1) m = fmaxf(m, __shfl_xor_sync(0xffffffffu, m, o));
    if (lane == 0) red[warp] = m;
    __syncthreads();
    m = red[0];
    #pragma unroll
    for (int w = 1; w < 8; w++) m = fmaxf(m, red[w]);
    __syncthreads();

    // exp + sum reduce
    float sum = 0.f;
    #pragma unroll
    for (int i = 0; i < 8; i++) { v[i] = __expf(v[i] - m); sum += v[i]; }
    #pragma unroll
    for (int o = 16; o > 0; o >>= 1) sum += __shfl_xor_sync(0xffffffffu, sum, o);
    if (lane == 0) red[warp] = sum;
    __syncthreads();
    sum = red[0];
    #pragma unroll
    for (int w = 1; w < 8; w++) sum += red[w];
    float inv = 1.f / sum;

    float4 o0 = make_float4(v[0] * inv, v[1] * inv, v[2] * inv, v[3] * inv);
    float4 o1 = make_float4(v[4] * inv, v[5] * inv, v[6] * inv, v[7] * inv);
    ((float4*)p)[tid * 2]     = o0;
    ((float4*)p)[tid * 2 + 1] = o1;
}

// ---------------------------------------------------------------------------
// Kernel 4: out[b] = P[b] @ v[b]. Same tiling as proj (BM=64,BN=128,BK=16).
// ---------------------------------------------------------------------------
__global__ __launch_bounds__(256) void out_kernel(float* __restrict__ out)
{
    __shared__ float As[16][64 + 4];
    __shared__ float Bs[16][128];

    const int b  = blockIdx.z;
    const int m0 = blockIdx.x * 64;
    const float* A  = g_s + (size_t)b * S_ * S_;
    const float* Bv = g_v + b * S_ * H_;
    float* C        = out + b * S_ * H_;

    const int tid = threadIdx.x;
    const int ty  = tid >> 5;
    const int tx  = tid & 31;

    float acc[8][4];
    #pragma unroll
    for (int i = 0; i < 8; i++)
        #pragma unroll
        for (int j = 0; j < 4; j++) acc[i][j] = 0.f;

    for (int k0 = 0; k0 < S_; k0 += 16) {
        #pragma unroll
        for (int i = 0; i < 4; i++) {
            int lin = tid + i * 256;
            int r = lin >> 4, c = lin & 15;
            As[c][r] = A[(size_t)(m0 + r) * S_ + k0 + c];
        }
        #pragma unroll
        for (int i = 0; i < 8; i++) {
            int lin = tid + i * 256;
            int r = lin >> 7, c = lin & 127;
            Bs[r][c] = Bv[(k0 + r) * H_ + c];
        }
        __syncthreads();

        #pragma unroll
        for (int kk = 0; kk < 16; kk++) {
            float4 a0 = *(const float4*)(&As[kk][ty * 8]);
            float4 a1 = *(const float4*)(&As[kk][ty * 8 + 4]);
            float4 bv = *(const float4*)(&Bs[kk][tx * 4]);
            float a[8] = {a0.x, a0.y, a0.z, a0.w, a1.x, a1.y, a1.z, a1.w};
            float bb[4] = {bv.x, bv.y, bv.z, bv.w};
            #pragma unroll
            for (int i = 0; i < 8; i++)
                #pragma unroll
                for (int j = 0; j < 4; j++)
                    acc[i][j] = fmaf(a[i], bb[j], acc[i][j]);
        }
        __syncthreads();
    }

    #pragma unroll
    for (int i = 0; i < 8; i++) {
        float4 v = make_float4(acc[i][0], acc[i][1], acc[i][2], acc[i][3]);
        *(float4*)&C[(m0 + ty * 8 + i) * H_ + tx * 4] = v;
    }
}

// ---------------------------------------------------------------------------
extern "C" void kernel_launch(void* const* d_in, const int* in_sizes, int n_in,
                              void* d_out, int out_size)
{
    const float* x  = (const float*)d_in[0];
    const float* Wq = (const float*)d_in[1];
    const float* Wk = (const float*)d_in[2];
    const float* Wv = (const float*)d_in[3];
    float* out = (float*)d_out;

    (void)in_sizes; (void)n_in; (void)out_size;

    // 1) projections: 16384 rows / 64 per block, z = {q,k,v}
    proj_kernel<<<dim3(S_ * B_ / 64, 1, 3), 256>>>(x, Wq, Wk, Wv);

    // 2) scores: 64x64 tiles over [2048, 2048] per batch
    scores_kernel<<<dim3(S_ / 64, S_ / 64, B_), 256>>>();

    // 3) softmax: one block per row
    softmax_kernel<<<dim3(B_ * S_), 256>>>();

    // 4) out = P @ v
    out_kernel<<<dim3(S_ / 64, 1, B_), 256>>>(out);
}

// round 2
// speedup vs baseline: 2.0458x; 2.0458x over previous
#include <cuda_runtime.h>

#define B_ 8
#define S_ 2048
#define E_ 4096
#define H_ 128

// Scratch (__device__ globals: allocation-free rule)
__device__ float g_q[B_ * S_ * H_];
__device__ float g_k[B_ * S_ * H_];
__device__ float g_v[B_ * S_ * H_];
__device__ float g_s[(size_t)B_ * S_ * S_];

// Round-to-nearest into TF32 (removes truncation bias of raw HMMA input).
__device__ __forceinline__ float to_tf32(float x) {
    float y;
    asm("cvt.rna.tf32.f32 %0, %1;" : "=f"(y) : "f"(x));
    return y;
}

// D += A*B   (m16n8k8, tf32 in, fp32 accum)
__device__ __forceinline__ void mma8(float* d, const unsigned* a, const unsigned* b) {
    asm volatile(
        "mma.sync.aligned.m16n8k8.row.col.f32.tf32.tf32.f32 "
        "{%0,%1,%2,%3}, {%4,%5,%6,%7}, {%8,%9}, {%0,%1,%2,%3};\n"
        : "+f"(d[0]), "+f"(d[1]), "+f"(d[2]), "+f"(d[3])
        : "r"(a[0]), "r"(a[1]), "r"(a[2]), "r"(a[3]), "r"(b[0]), "r"(b[1]));
}

// ---------------------------------------------------------------------------
// Kernel 1: projections. C[16384,128] = X[16384,4096] @ W[4096,128]
// BM=128, BN=128, BK=32; 8 warps (4m x 2n); warp tile 32x64 (2x8 mma tiles).
// ---------------------------------------------------------------------------
__global__ __launch_bounds__(256) void proj_mma(
    const float* __restrict__ x,
    const float* __restrict__ Wq,
    const float* __restrict__ Wk,
    const float* __restrict__ Wv)
{
    __shared__ float As[128][36];   // [m][k], pad -> conflict-free frag loads
    __shared__ float Bs[32][132];   // [k][n]

    const float* W = (blockIdx.z == 0) ? Wq : (blockIdx.z == 1) ? Wk : Wv;
    float* C       = (blockIdx.z == 0) ? g_q : (blockIdx.z == 1) ? g_k : g_v;

    const int tid  = threadIdx.x;
    const int warp = tid >> 5, lane = tid & 31;
    const int wm = warp >> 1, wn = warp & 1;
    const int g = lane >> 2, t = lane & 3;
    const int m0 = blockIdx.x * 128;

    float acc[2][8][4];
    #pragma unroll
    for (int i = 0; i < 2; i++)
        #pragma unroll
        for (int j = 0; j < 8; j++)
            #pragma unroll
            for (int r = 0; r < 4; r++) acc[i][j][r] = 0.f;

    for (int k0 = 0; k0 < E_; k0 += 32) {
        #pragma unroll
        for (int i = 0; i < 4; i++) {           // A tile 128x32
            int lin = tid + i * 256;
            int r = lin >> 3, c = (lin & 7) * 4;
            float4 v = *(const float4*)&x[(size_t)(m0 + r) * E_ + k0 + c];
            v.x = to_tf32(v.x); v.y = to_tf32(v.y);
            v.z = to_tf32(v.z); v.w = to_tf32(v.w);
            *(float4*)&As[r][c] = v;
        }
        #pragma unroll
        for (int i = 0; i < 4; i++) {           // B tile 32x128
            int lin = tid + i * 256;
            int r = lin >> 5, c = (lin & 31) * 4;
            float4 v = *(const float4*)&W[(size_t)(k0 + r) * H_ + c];
            v.x = to_tf32(v.x); v.y = to_tf32(v.y);
            v.z = to_tf32(v.z); v.w = to_tf32(v.w);
            *(float4*)&Bs[r][c] = v;
        }
        __syncthreads();

        #pragma unroll
        for (int ks = 0; ks < 4; ks++) {
            const int kb = ks * 8;
            unsigned a[2][4], b[8][2];
            #pragma unroll
            for (int mt = 0; mt < 2; mt++) {
                int m = wm * 32 + mt * 16;
                a[mt][0] = __float_as_uint(As[m + g][kb + t]);
                a[mt][1] = __float_as_uint(As[m + 8 + g][kb + t]);
                a[mt][2] = __float_as_uint(As[m + g][kb + t + 4]);
                a[mt][3] = __float_as_uint(As[m + 8 + g][kb + t + 4]);
            }
            #pragma unroll
            for (int nt = 0; nt < 8; nt++) {
                int n = wn * 64 + nt * 8;
                b[nt][0] = __float_as_uint(Bs[kb + t][n + g]);
                b[nt][1] = __float_as_uint(Bs[kb + t + 4][n + g]);
            }
            #pragma unroll
            for (int mt = 0; mt < 2; mt++)
                #pragma unroll
                for (int nt = 0; nt < 8; nt++)
                    mma8(acc[mt][nt], a[mt], b[nt]);
        }
        __syncthreads();
    }

    #pragma unroll
    for (int mt = 0; mt < 2; mt++)
        #pragma unroll
        for (int nt = 0; nt < 8; nt++) {
            int row = m0 + wm * 32 + mt * 16 + g;
            int col = wn * 64 + nt * 8 + t * 2;
            *(float2*)&C[(size_t)row * H_ + col] =
                make_float2(acc[mt][nt][0], acc[mt][nt][1]);
            *(float2*)&C[(size_t)(row + 8) * H_ + col] =
                make_float2(acc[mt][nt][2], acc[mt][nt][3]);
        }
}

// ---------------------------------------------------------------------------
// Kernel 2: scores. S[b] = q[b] @ k[b]^T * scale.  BM=BN=128, K=128 (BK=32).
// K tile stays in native [s][h] layout; B-frags read Ks[n][k] directly.
// ---------------------------------------------------------------------------
__global__ __launch_bounds__(256) void scores_mma()
{
    __shared__ float Qs[128][36];   // [m][k]
    __shared__ float Ks[128][36];   // [n][k]

    const int b  = blockIdx.z;
    const int m0 = blockIdx.y * 128;
    const int n0 = blockIdx.x * 128;
    const float* q = g_q + b * S_ * H_;
    const float* k = g_k + b * S_ * H_;
    float* s = g_s + (size_t)b * S_ * S_;

    const int tid  = threadIdx.x;
    const int warp = tid >> 5, lane = tid & 31;
    const int wm = warp >> 1, wn = warp & 1;
    const int g = lane >> 2, t = lane & 3;

    float acc[2][8][4];
    #pragma unroll
    for (int i = 0; i < 2; i++)
        #pragma unroll
        for (int j = 0; j < 8; j++)
            #pragma unroll
            for (int r = 0; r < 4; r++) acc[i][j][r] = 0.f;

    for (int k0 = 0; k0 < H_; k0 += 32) {
        #pragma unroll
        for (int i = 0; i < 4; i++) {
            int lin = tid + i * 256;
            int r = lin >> 3, c = (lin & 7) * 4;
            float4 vq = *(const float4*)&q[(size_t)(m0 + r) * H_ + k0 + c];
            vq.x = to_tf32(vq.x); vq.y = to_tf32(vq.y);
            vq.z = to_tf32(vq.z); vq.w = to_tf32(vq.w);
            *(float4*)&Qs[r][c] = vq;
            float4 vk = *(const float4*)&k[(size_t)(n0 + r) * H_ + k0 + c];
            vk.x = to_tf32(vk.x); vk.y = to_tf32(vk.y);
            vk.z = to_tf32(vk.z); vk.w = to_tf32(vk.w);
            *(float4*)&Ks[r][c] = vk;
        }
        __syncthreads();

        #pragma unroll
        for (int ks = 0; ks < 4; ks++) {
            const int kb = ks * 8;
            unsigned a[2][4], bfr[8][2];
            #pragma unroll
            for (int mt = 0; mt < 2; mt++) {
                int m = wm * 32 + mt * 16;
                a[mt][0] = __float_as_uint(Qs[m + g][kb + t]);
                a[mt][1] = __float_as_uint(Qs[m + 8 + g][kb + t]);
                a[mt][2] = __float_as_uint(Qs[m + g][kb + t + 4]);
                a[mt][3] = __float_as_uint(Qs[m + 8 + g][kb + t + 4]);
            }
            #pragma unroll
            for (int nt = 0; nt < 8; nt++) {
                int n = wn * 64 + nt * 8;
                bfr[nt][0] = __float_as_uint(Ks[n + g][kb + t]);
                bfr[nt][1] = __float_as_uint(Ks[n + g][kb + t + 4]);
            }
            #pragma unroll
            for (int mt = 0; mt < 2; mt++)
                #pragma unroll
                for (int nt = 0; nt < 8; nt++)
                    mma8(acc[mt][nt], a[mt], bfr[nt]);
        }
        __syncthreads();
    }

    const float scale = 0.08838834764831845f;  // 1/sqrt(128)
    #pragma unroll
    for (int mt = 0; mt < 2; mt++)
        #pragma unroll
        for (int nt = 0; nt < 8; nt++) {
            int row = m0 + wm * 32 + mt * 16 + g;
            int col = n0 + wn * 64 + nt * 8 + t * 2;
            *(float2*)&s[(size_t)row * S_ + col] =
                make_float2(acc[mt][nt][0] * scale, acc[mt][nt][1] * scale);
            *(float2*)&s[(size_t)(row + 8) * S_ + col] =
                make_float2(acc[mt][nt][2] * scale, acc[mt][nt][3] * scale);
        }
}

// ---------------------------------------------------------------------------
// Kernel 3: row softmax over 2048 cols; one block per row, row in registers.
// ---------------------------------------------------------------------------
__global__ __launch_bounds__(256) void softmax_kernel()
{
    __shared__ float red[8];
    float* p = g_s + (size_t)blockIdx.x * S_;
    const int tid  = threadIdx.x;
    const int lane = tid & 31;
    const int warp = tid >> 5;

    float4 v0 = ((const float4*)p)[tid * 2];
    float4 v1 = ((const float4*)p)[tid * 2 + 1];
    float v[8] = {v0.x, v0.y, v0.z, v0.w, v1.x, v1.y, v1.z, v1.w};

    float m = v[0];
    #pragma unroll
    for (int i = 1; i < 8; i++) m = fmaxf(m, v[i]);
    #pragma unroll
    for (int o = 16; o > 0; o >>= 1) m = fmaxf(m, __shfl_xor_sync(0xffffffffu, m, o));
    if (lane == 0) red[warp] = m;
    __syncthreads();
    m = red[0];
    #pragma unroll
    for (int w = 1; w < 8; w++) m = fmaxf(m, red[w]);
    __syncthreads();

    float sum = 0.f;
    #pragma unroll
    for (int i = 0; i < 8; i++) { v[i] = __expf(v[i] - m); sum += v[i]; }
    #pragma unroll
    for (int o = 16; o > 0; o >>= 1) sum += __shfl_xor_sync(0xffffffffu, sum, o);
    if (lane == 0) red[warp] = sum;
    __syncthreads();
    sum = red[0];
    #pragma unroll
    for (int w = 1; w < 8; w++) sum += red[w];
    float inv = 1.f / sum;

    ((float4*)p)[tid * 2]     = make_float4(v[0]*inv, v[1]*inv, v[2]*inv, v[3]*inv);
    ((float4*)p)[tid * 2 + 1] = make_float4(v[4]*inv, v[5]*inv, v[6]*inv, v[7]*inv);
}

// ---------------------------------------------------------------------------
// Kernel 4: out[b] = P[b] @ v[b].  Same shape as proj, K=2048.
// ---------------------------------------------------------------------------
__global__ __launch_bounds__(256) void out_mma(float* __restrict__ out)
{
    __shared__ float As[128][36];   // [m][k] from P
    __shared__ float Bs[32][132];   // [k][n] from V

    const int b  = blockIdx.z;
    const int m0 = blockIdx.x * 128;
    const float* A  = g_s + (size_t)b * S_ * S_;
    const float* Bv = g_v + b * S_ * H_;
    float* C        = out + b * S_ * H_;

    const int tid  = threadIdx.x;
    const int warp = tid >> 5, lane = tid & 31;
    const int wm = warp >> 1, wn = warp & 1;
    const int g = lane >> 2, t = lane & 3;

    float acc[2][8][4];
    #pragma unroll
    for (int i = 0; i < 2; i++)
        #pragma unroll
        for (int j = 0; j < 8; j++)
            #pragma unroll
            for (int r = 0; r < 4; r++) acc[i][j][r] = 0.f;

    for (int k0 = 0; k0 < S_; k0 += 32) {
        #pragma unroll
        for (int i = 0; i < 4; i++) {
            int lin = tid + i * 256;
            int r = lin >> 3, c = (lin & 7) * 4;
            float4 v = *(const float4*)&A[(size_t)(m0 + r) * S_ + k0 + c];
            v.x = to_tf32(v.x); v.y = to_tf32(v.y);
            v.z = to_tf32(v.z); v.w = to_tf32(v.w);
            *(float4*)&As[r][c] = v;
        }
        #pragma unroll
        for (int i = 0; i < 4; i++) {
            int lin = tid + i * 256;
            int r = lin >> 5, c = (lin & 31) * 4;
            float4 v = *(const float4*)&Bv[(size_t)(k0 + r) * H_ + c];
            v.x = to_tf32(v.x); v.y = to_tf32(v.y);
            v.z = to_tf32(v.z); v.w = to_tf32(v.w);
            *(float4*)&Bs[r][c] = v;
        }
        __syncthreads();

        #pragma unroll
        for (int ks = 0; ks < 4; ks++) {
            const int kb = ks * 8;
            unsigned a[2][4], bfr[8][2];
            #pragma unroll
            for (int mt = 0; mt < 2; mt++) {
                int m = wm * 32 + mt * 16;
                a[mt][0] = __float_as_uint(As[m + g][kb + t]);
                a[mt][1] = __float_as_uint(As[m + 8 + g][kb + t]);
                a[mt][2] = __float_as_uint(As[m + g][kb + t + 4]);
                a[mt][3] = __float_as_uint(As[m + 8 + g][kb + t + 4]);
            }
            #pragma unroll
            for (int nt = 0; nt < 8; nt++) {
                int n = wn * 64 + nt * 8;
                bfr[nt][0] = __float_as_uint(Bs[kb + t][n + g]);
                bfr[nt][1] = __float_as_uint(Bs[kb + t + 4][n + g]);
            }
            #pragma unroll
            for (int mt = 0; mt < 2; mt++)
                #pragma unroll
                for (int nt = 0; nt < 8; nt++)
                    mma8(acc[mt][nt], a[mt], bfr[nt]);
        }
        __syncthreads();
    }

    #pragma unroll
    for (int mt = 0; mt < 2; mt++)
        #pragma unroll
        for (int nt = 0; nt < 8; nt++) {
            int row = m0 + wm * 32 + mt * 16 + g;
            int col = wn * 64 + nt * 8 + t * 2;
            *(float2*)&C[(size_t)row * H_ + col] =
                make_float2(acc[mt][nt][0], acc[mt][nt][1]);
            *(float2*)&C[(size_t)(row + 8) * H_ + col] =
                make_float2(acc[mt][nt][2], acc[mt][nt][3]);
        }
}

// ---------------------------------------------------------------------------
extern "C" void kernel_launch(void* const* d_in, const int* in_sizes, int n_in,
                              void* d_out, int out_size)
{
    const float* x  = (const float*)d_in[0];
    const float* Wq = (const float*)d_in[1];
    const float* Wk = (const float*)d_in[2];
    const float* Wv = (const float*)d_in[3];
    float* out = (float*)d_out;
    (void)in_sizes; (void)n_in; (void)out_size;

    proj_mma<<<dim3(S_ * B_ / 128, 1, 3), 256>>>(x, Wq, Wk, Wv);
    scores_mma<<<dim3(S_ / 128, S_ / 128, B_), 256>>>();
    softmax_kernel<<<dim3(B_ * S_), 256>>>();
    out_mma<<<dim3(S_ / 128, 1, B_), 256>>>(out);
}

// round 4
// speedup vs baseline: 4.1478x; 2.0275x over previous
#include <cuda_runtime.h>
#include <cuda_fp16.h>

#define B_ 8
#define S_ 2048
#define E_ 4096
#define H_ 128

// q,k,v in fp16 (q pre-scaled by 1/sqrt(H)*log2(e)); 16B-aligned for cp.async/ldsm
__device__ __align__(16) __half g_q[B_ * S_ * H_];
__device__ __align__(16) __half g_k[B_ * S_ * H_];
__device__ __align__(16) __half g_v[B_ * S_ * H_];

// ---------------------------------------------------------------------------
__device__ __forceinline__ void ldsm4(unsigned* r, unsigned addr) {
    asm volatile("ldmatrix.sync.aligned.m8n8.x4.shared.b16 {%0,%1,%2,%3}, [%4];"
                 : "=r"(r[0]), "=r"(r[1]), "=r"(r[2]), "=r"(r[3]) : "r"(addr));
}
__device__ __forceinline__ void ldsm4t(unsigned* r, unsigned addr) {
    asm volatile("ldmatrix.sync.aligned.m8n8.x4.trans.shared.b16 {%0,%1,%2,%3}, [%4];"
                 : "=r"(r[0]), "=r"(r[1]), "=r"(r[2]), "=r"(r[3]) : "r"(addr));
}
// D += A*B, m16n8k16, f16 in / f32 accum
__device__ __forceinline__ void mma16816(float* d, const unsigned* a, const unsigned* b) {
    asm volatile(
        "mma.sync.aligned.m16n8k16.row.col.f32.f16.f16.f32 "
        "{%0,%1,%2,%3}, {%4,%5,%6,%7}, {%8,%9}, {%0,%1,%2,%3};"
        : "+f"(d[0]), "+f"(d[1]), "+f"(d[2]), "+f"(d[3])
        : "r"(a[0]), "r"(a[1]), "r"(a[2]), "r"(a[3]), "r"(b[0]), "r"(b[1]));
}
__device__ __forceinline__ void cp16(unsigned dst, const void* src) {
    asm volatile("cp.async.cg.shared.global [%0], [%1], 16;" :: "r"(dst), "l"(src));
}
__device__ __forceinline__ float ex2(float x) {
    float y; asm("ex2.approx.ftz.f32 %0, %1;" : "=f"(y) : "f"(x)); return y;
}
__device__ __forceinline__ unsigned packh2(float a, float b) {
    __half2 h = __floats2half2_rn(a, b);
    return *(unsigned*)&h;
}

// ---------------------------------------------------------------------------
// Projections: C[16384,128] = x[16384,4096] @ W[4096,128]  (fp16 mma)
// BM=128, BN=128, BK=32; 8 warps (4m x 2n); warp 32x64 = 2 m-tiles x 8 n-tiles.
// Double-buffered smem; global loads staged in regs.
// ---------------------------------------------------------------------------
#define XS_STRIDE 40    // 32 + 8 halfs
#define WS_STRIDE 136   // 128 + 8 halfs
#define XS_TILE (128 * XS_STRIDE)
#define WS_TILE (32 * WS_STRIDE)

__global__ __launch_bounds__(256, 2) void proj_fp16(
    const float* __restrict__ x,
    const float* __restrict__ Wq,
    const float* __restrict__ Wk,
    const float* __restrict__ Wv)
{
    extern __shared__ __half psm[];
    __half* Xs = psm;                 // [2][128][40]
    __half* Ws = psm + 2 * XS_TILE;   // [2][32][136]

    const int z = blockIdx.z;
    const float* W = (z == 0) ? Wq : (z == 1) ? Wk : Wv;
    __half* C      = (z == 0) ? g_q : (z == 1) ? g_k : g_v;
    const float csc = (z == 0) ? (float)(0.08838834764831845 * 1.4426950408889634) : 1.0f;

    const int m0   = blockIdx.x * 128;
    const int tid  = threadIdx.x;
    const int warp = tid >> 5, lane = tid & 31;
    const int wm = warp >> 1, wn = warp & 1;
    const int g = lane >> 2, t = lane & 3;
    const int r8 = lane & 7, quad = lane >> 3;

    const unsigned offA_x = ((r8 + ((quad & 1) << 3)) * XS_STRIDE + ((quad >> 1) << 3)) * 2;
    const unsigned offA_w = ((r8 + ((quad & 1) << 3)) * WS_STRIDE + ((quad >> 1) << 3)) * 2;
    const unsigned xs_u = (unsigned)__cvta_generic_to_shared(Xs);
    const unsigned ws_u = (unsigned)__cvta_generic_to_shared(Ws);

    int xg_r[2], xg_c[2], wg_r[2], wg_c[2];
    #pragma unroll
    for (int gi = 0; gi < 2; gi++) {
        int gid = tid + gi * 256;
        xg_r[gi] = gid >> 2;  xg_c[gi] = (gid & 3) << 3;
        wg_r[gi] = gid >> 4;  wg_c[gi] = (gid & 15) << 3;
    }

    float4 xr[2][2], wr[2][2];
    auto ldg_tiles = [&](int k0) {
        #pragma unroll
        for (int gi = 0; gi < 2; gi++) {
            const float* px = x + (size_t)(m0 + xg_r[gi]) * E_ + k0 + xg_c[gi];
            xr[gi][0] = *(const float4*)px;
            xr[gi][1] = *(const float4*)(px + 4);
            const float* pw = W + (size_t)(k0 + wg_r[gi]) * H_ + wg_c[gi];
            wr[gi][0] = *(const float4*)pw;
            wr[gi][1] = *(const float4*)(pw + 4);
        }
    };
    auto sts_tiles = [&](int st) {
        #pragma unroll
        for (int gi = 0; gi < 2; gi++) {
            uint4 ux;
            ux.x = packh2(xr[gi][0].x, xr[gi][0].y);
            ux.y = packh2(xr[gi][0].z, xr[gi][0].w);
            ux.z = packh2(xr[gi][1].x, xr[gi][1].y);
            ux.w = packh2(xr[gi][1].z, xr[gi][1].w);
            *(uint4*)(Xs + st * XS_TILE + xg_r[gi] * XS_STRIDE + xg_c[gi]) = ux;
            uint4 uw;
            uw.x = packh2(wr[gi][0].x, wr[gi][0].y);
            uw.y = packh2(wr[gi][0].z, wr[gi][0].w);
            uw.z = packh2(wr[gi][1].x, wr[gi][1].y);
            uw.w = packh2(wr[gi][1].z, wr[gi][1].w);
            *(uint4*)(Ws + st * WS_TILE + wg_r[gi] * WS_STRIDE + wg_c[gi]) = uw;
        }
    };

    float acc[2][8][4];
    #pragma unroll
    for (int i = 0; i < 2; i++)
        #pragma unroll
        for (int j = 0; j < 8; j++)
            #pragma unroll
            for (int r = 0; r < 4; r++) acc[i][j][r] = 0.f;

    ldg_tiles(0);
    sts_tiles(0);
    __syncthreads();

    const int NIT = E_ / 32;
    for (int it = 0; it < NIT; it++) {
        const int st = it & 1;
        if (it + 1 < NIT) ldg_tiles((it + 1) * 32);

        #pragma unroll
        for (int kb = 0; kb < 2; kb++) {
            unsigned a[2][4];
            #pragma unroll
            for (int mt = 0; mt < 2; mt++)
                ldsm4(a[mt], xs_u + (st * XS_TILE + (wm * 32 + mt * 16) * XS_STRIDE + kb * 16) * 2 + offA_x);
            #pragma unroll
            for (int d2 = 0; d2 < 4; d2++) {
                unsigned bb[4];
                ldsm4t(bb, ws_u + (st * WS_TILE + (kb * 16) * WS_STRIDE + wn * 64 + d2 * 16) * 2 + offA_w);
                #pragma unroll
                for (int mt = 0; mt < 2; mt++) {
                    mma16816(acc[mt][d2 * 2],     a[mt], bb);
                    mma16816(acc[mt][d2 * 2 + 1], a[mt], bb + 2);
                }
            }
        }
        if (it + 1 < NIT) sts_tiles(st ^ 1);
        __syncthreads();
    }

    #pragma unroll
    for (int mt = 0; mt < 2; mt++)
        #pragma unroll
        for (int nt = 0; nt < 8; nt++) {
            int row = m0 + wm * 32 + mt * 16 + g;
            int col = wn * 64 + nt * 8 + t * 2;
            *(__half2*)&C[(size_t)row * H_ + col] =
                __floats2half2_rn(acc[mt][nt][0] * csc, acc[mt][nt][1] * csc);
            *(__half2*)&C[(size_t)(row + 8) * H_ + col] =
                __floats2half2_rn(acc[mt][nt][2] * csc, acc[mt][nt][3] * csc);
        }
}

// ---------------------------------------------------------------------------
// Flash attention: per CTA 128 q-rows x full KV sweep. 8 warps x 16 rows.
// Online softmax in exp2 domain (scale*log2e folded into stored Q).
// P stays in registers (accumulator->A-fragment layout identity).
// ---------------------------------------------------------------------------
#define FS_STRIDE 136
#define FS_TILE (128 * FS_STRIDE)   // halfs per tile

__global__ __launch_bounds__(256, 1) void flash_kernel(float* __restrict__ out)
{
    extern __shared__ __half fsm[];
    // layout: Q | K0 | K1 | V0 | V1
    const unsigned q_u  = (unsigned)__cvta_generic_to_shared(fsm);
    const unsigned k_u0 = q_u + FS_TILE * 2;
    const unsigned k_u1 = q_u + FS_TILE * 4;
    const unsigned v_u0 = q_u + FS_TILE * 6;
    const unsigned v_u1 = q_u + FS_TILE * 8;

    const int b = blockIdx.y;
    const int q0 = blockIdx.x * 128;
    const int tid = threadIdx.x;
    const int warp = tid >> 5, lane = tid & 31;
    const int g = lane >> 2, t = lane & 3;
    const int r8 = lane & 7, quad = lane >> 3;

    const __half* gQ = g_q + ((size_t)b * S_ + q0) * H_;
    const __half* gK = g_k + (size_t)b * S_ * H_;
    const __half* gV = g_v + (size_t)b * S_ * H_;

    const unsigned offA = ((r8 + ((quad & 1) << 3)) * FS_STRIDE + ((quad >> 1) << 3)) * 2;
    const unsigned offB = ((r8 + ((quad >> 1) << 3)) * FS_STRIDE + ((quad & 1) << 3)) * 2;

    int ch_r[8], ch_c[8];
    #pragma unroll
    for (int i = 0; i < 8; i++) {
        int id = tid + i * 256;
        ch_r[i] = id >> 4;
        ch_c[i] = (id & 15) << 3;
    }

    // prologue: Q + K0 + V0
    #pragma unroll
    for (int i = 0; i < 8; i++) {
        unsigned so = (ch_r[i] * FS_STRIDE + ch_c[i]) * 2;
        const size_t go = (size_t)ch_r[i] * H_ + ch_c[i];
        cp16(q_u + so,  gQ + go);
        cp16(k_u0 + so, gK + go);
        cp16(v_u0 + so, gV + go);
    }
    asm volatile("cp.async.commit_group;");

    float o[16][4];
    #pragma unroll
    for (int i = 0; i < 16; i++)
        #pragma unroll
        for (int r = 0; r < 4; r++) o[i][r] = 0.f;
    float mr0 = -1e30f, mr1 = -1e30f, l0 = 0.f, l1 = 0.f;

    asm volatile("cp.async.wait_group 0;");
    __syncthreads();

    for (int j = 0; j < S_ / 128; j++) {
        const unsigned kb_u = (j & 1) ? k_u1 : k_u0;
        const unsigned vb_u = (j & 1) ? v_u1 : v_u0;

        if (j + 1 < S_ / 128) {
            const unsigned kn_u = (j & 1) ? k_u0 : k_u1;
            const unsigned vn_u = (j & 1) ? v_u0 : v_u1;
            const __half* srcK = gK + (size_t)(j + 1) * 128 * H_;
            const __half* srcV = gV + (size_t)(j + 1) * 128 * H_;
            #pragma unroll
            for (int i = 0; i < 8; i++) {
                unsigned so = (ch_r[i] * FS_STRIDE + ch_c[i]) * 2;
                const size_t go = (size_t)ch_r[i] * H_ + ch_c[i];
                cp16(kn_u + so, srcK + go);
                cp16(vn_u + so, srcV + go);
            }
            asm volatile("cp.async.commit_group;");
        }

        // ---- scores ----
        float s[16][4];
        #pragma unroll
        for (int i = 0; i < 16; i++)
            #pragma unroll
            for (int r = 0; r < 4; r++) s[i][r] = 0.f;

        #pragma unroll
        for (int kb = 0; kb < 8; kb++) {
            unsigned a[4];
            ldsm4(a, q_u + ((warp * 16) * FS_STRIDE + kb * 16) * 2 + offA);
            #pragma unroll
            for (int n2 = 0; n2 < 8; n2++) {
                unsigned bb[4];
                ldsm4(bb, kb_u + ((n2 * 16) * FS_STRIDE + kb * 16) * 2 + offB);
                mma16816(s[n2 * 2],     a, bb);
                mma16816(s[n2 * 2 + 1], a, bb + 2);
            }
        }

        // ---- online softmax (exp2 domain) ----
        float mx0 = -1e30f, mx1 = -1e30f;
        #pragma unroll
        for (int i = 0; i < 16; i++) {
            mx0 = fmaxf(mx0, fmaxf(s[i][0], s[i][1]));
            mx1 = fmaxf(mx1, fmaxf(s[i][2], s[i][3]));
        }
        mx0 = fmaxf(mx0, __shfl_xor_sync(0xffffffffu, mx0, 1));
        mx0 = fmaxf(mx0, __shfl_xor_sync(0xffffffffu, mx0, 2));
        mx1 = fmaxf(mx1, __shfl_xor_sync(0xffffffffu, mx1, 1));
        mx1 = fmaxf(mx1, __shfl_xor_sync(0xffffffffu, mx1, 2));

        const float mn0 = fmaxf(mr0, mx0), mn1 = fmaxf(mr1, mx1);
        const float cor0 = ex2(mr0 - mn0), cor1 = ex2(mr1 - mn1);
        mr0 = mn0; mr1 = mn1;
        l0 *= cor0; l1 *= cor1;
        #pragma unroll
        for (int i = 0; i < 16; i++) {
            o[i][0] *= cor0; o[i][1] *= cor0;
            o[i][2] *= cor1; o[i][3] *= cor1;
        }

        unsigned p[8][4];
        float s0 = 0.f, s1 = 0.f;
        #pragma unroll
        for (int n2 = 0; n2 < 8; n2++) {
            float e0 = ex2(s[2 * n2][0] - mn0), e1 = ex2(s[2 * n2][1] - mn0);
            float e2 = ex2(s[2 * n2][2] - mn1), e3 = ex2(s[2 * n2][3] - mn1);
            float f0 = ex2(s[2 * n2 + 1][0] - mn0), f1 = ex2(s[2 * n2 + 1][1] - mn0);
            float f2 = ex2(s[2 * n2 + 1][2] - mn1), f3 = ex2(s[2 * n2 + 1][3] - mn1);
            s0 += e0 + e1 + f0 + f1;
            s1 += e2 + e3 + f2 + f3;
            p[n2][0] = packh2(e0, e1);
            p[n2][1] = packh2(e2, e3);
            p[n2][2] = packh2(f0, f1);
            p[n2][3] = packh2(f2, f3);
        }
        l0 += s0; l1 += s1;

        // ---- PV: o += P @ V ----
        #pragma unroll
        for (int kb = 0; kb < 8; kb++) {
            #pragma unroll
            for (int d2 = 0; d2 < 8; d2++) {
                unsigned bb[4];
                ldsm4t(bb, vb_u + ((kb * 16) * FS_STRIDE + d2 * 16) * 2 + offA);
                mma16816(o[d2 * 2],     p[kb], bb);
                mma16816(o[d2 * 2 + 1], p[kb], bb + 2);
            }
        }

        asm volatile("cp.async.wait_group 0;");
        __syncthreads();
    }

    // epilogue
    l0 += __shfl_xor_sync(0xffffffffu, l0, 1);
    l0 += __shfl_xor_sync(0xffffffffu, l0, 2);
    l1 += __shfl_xor_sync(0xffffffffu, l1, 1);
    l1 += __shfl_xor_sync(0xffffffffu, l1, 2);
    const float inv0 = 1.f / l0, inv1 = 1.f / l1;

    const size_t row0 = (size_t)b * S_ + q0 + warp * 16 + g;
    #pragma unroll
    for (int nt = 0; nt < 16; nt++) {
        int col = nt * 8 + t * 2;
        *(float2*)&out[row0 * H_ + col] =
            make_float2(o[nt][0] * inv0, o[nt][1] * inv0);
        *(float2*)&out[(row0 + 8) * H_ + col] =
            make_float2(o[nt][2] * inv1, o[nt][3] * inv1);
    }
}

// ---------------------------------------------------------------------------
extern "C" void kernel_launch(void* const* d_in, const int* in_sizes, int n_in,
                              void* d_out, int out_size)
{
    const float* x  = (const float*)d_in[0];
    const float* Wq = (const float*)d_in[1];
    const float* Wk = (const float*)d_in[2];
    const float* Wv = (const float*)d_in[3];
    float* out = (float*)d_out;
    (void)in_sizes; (void)n_in; (void)out_size;

    const int proj_smem  = (2 * XS_TILE + 2 * WS_TILE) * 2;   // 37888 B
    const int flash_smem = 5 * FS_TILE * 2;                   // 174080 B

    cudaFuncSetAttribute(flash_kernel,
                         cudaFuncAttributeMaxDynamicSharedMemorySize, flash_smem);

    proj_fp16<<<dim3(128, 1, 3), 256, proj_smem>>>(x, Wq, Wk, Wv);
    flash_kernel<<<dim3(S_ / 128, B_), 256, flash_smem>>>(out);
}

// round 6
// speedup vs baseline: 4.7351x; 1.1416x over previous
#include <cuda_runtime.h>
#include <cuda_fp16.h>

#define B_ 8
#define S_ 2048
#define E_ 4096
#define H_ 128

// fp16 staging (16B aligned for cp.async/ldsm)
__device__ __align__(16) __half g_x[B_ * S_ * E_];    // 134 MB
__device__ __align__(16) __half g_wq[E_ * H_];
__device__ __align__(16) __half g_wk[E_ * H_];
__device__ __align__(16) __half g_wv[E_ * H_];
__device__ __align__(16) __half g_q[B_ * S_ * H_];
__device__ __align__(16) __half g_k[B_ * S_ * H_];
__device__ __align__(16) __half g_v[B_ * S_ * H_];

// ---------------------------------------------------------------------------
__device__ __forceinline__ void ldsm4(unsigned* r, unsigned addr) {
    asm volatile("ldmatrix.sync.aligned.m8n8.x4.shared.b16 {%0,%1,%2,%3}, [%4];"
                 : "=r"(r[0]), "=r"(r[1]), "=r"(r[2]), "=r"(r[3]) : "r"(addr));
}
__device__ __forceinline__ void ldsm4t(unsigned* r, unsigned addr) {
    asm volatile("ldmatrix.sync.aligned.m8n8.x4.trans.shared.b16 {%0,%1,%2,%3}, [%4];"
                 : "=r"(r[0]), "=r"(r[1]), "=r"(r[2]), "=r"(r[3]) : "r"(addr));
}
__device__ __forceinline__ void mma16816(float* d, const unsigned* a, const unsigned* b) {
    asm volatile(
        "mma.sync.aligned.m16n8k16.row.col.f32.f16.f16.f32 "
        "{%0,%1,%2,%3}, {%4,%5,%6,%7}, {%8,%9}, {%0,%1,%2,%3};"
        : "+f"(d[0]), "+f"(d[1]), "+f"(d[2]), "+f"(d[3])
        : "r"(a[0]), "r"(a[1]), "r"(a[2]), "r"(a[3]), "r"(b[0]), "r"(b[1]));
}
__device__ __forceinline__ void cp16(unsigned dst, const void* src) {
    asm volatile("cp.async.cg.shared.global [%0], [%1], 16;" :: "r"(dst), "l"(src));
}
__device__ __forceinline__ float ex2(float x) {
    float y; asm("ex2.approx.ftz.f32 %0, %1;" : "=f"(y) : "f"(x)); return y;
}
__device__ __forceinline__ unsigned packh2(float a, float b) {
    __half2 h = __floats2half2_rn(a, b);
    return *(unsigned*)&h;
}

// ---------------------------------------------------------------------------
// fp32 -> fp16 converters (streaming)
// ---------------------------------------------------------------------------
__global__ __launch_bounds__(256) void cvt_x_kernel(const float* __restrict__ x)
{
    const size_t i = ((size_t)blockIdx.x * 256 + threadIdx.x) * 8;
    float4 a = *(const float4*)(x + i);
    float4 b = *(const float4*)(x + i + 4);
    uint4 u;
    u.x = packh2(a.x, a.y); u.y = packh2(a.z, a.w);
    u.z = packh2(b.x, b.y); u.w = packh2(b.z, b.w);
    *(uint4*)(g_x + i) = u;
}

__global__ __launch_bounds__(256) void cvt_w_kernel(
    const float* __restrict__ Wq, const float* __restrict__ Wk,
    const float* __restrict__ Wv)
{
    const int z = blockIdx.y;
    const float* src = (z == 0) ? Wq : (z == 1) ? Wk : Wv;
    __half* dst      = (z == 0) ? g_wq : (z == 1) ? g_wk : g_wv;
    const size_t i = ((size_t)blockIdx.x * 256 + threadIdx.x) * 8;
    float4 a = *(const float4*)(src + i);
    float4 b = *(const float4*)(src + i + 4);
    uint4 u;
    u.x = packh2(a.x, a.y); u.y = packh2(a.z, a.w);
    u.z = packh2(b.x, b.y); u.w = packh2(b.z, b.w);
    *(uint4*)(dst + i) = u;
}

// ---------------------------------------------------------------------------
// Projections: C[16384,128] = g_x[16384,4096] @ W[4096,128]  (fp16, cp.async)
// BM=128, BN=128, BK=32; 4-stage cp.async pipeline; 8 warps (4m x 2n).
// ---------------------------------------------------------------------------
#define XS_STRIDE 40
#define WS_STRIDE 136
#define XS_TILE (128 * XS_STRIDE)   // halfs per stage
#define WS_TILE (32 * WS_STRIDE)
#define NSTAGE 4
#define PROJ_SMEM ((NSTAGE * XS_TILE + NSTAGE * WS_TILE) * 2)   // 75776 B

__global__ __launch_bounds__(256, 2) void proj_fp16(void)
{
    extern __shared__ __half psm[];
    __half* Xs = psm;                        // [4][128][40]
    __half* Ws = psm + NSTAGE * XS_TILE;     // [4][32][136]

    const int z = blockIdx.z;
    const __half* W = (z == 0) ? g_wq : (z == 1) ? g_wk : g_wv;
    __half* C       = (z == 0) ? g_q : (z == 1) ? g_k : g_v;
    const float csc = (z == 0) ? (float)(0.08838834764831845 * 1.4426950408889634) : 1.0f;

    const int m0   = blockIdx.x * 128;
    const int tid  = threadIdx.x;
    const int warp = tid >> 5, lane = tid & 31;
    const int wm = warp >> 1, wn = warp & 1;
    const int g = lane >> 2, t = lane & 3;
    const int r8 = lane & 7, quad = lane >> 3;

    const unsigned offA_x = ((r8 + ((quad & 1) << 3)) * XS_STRIDE + ((quad >> 1) << 3)) * 2;
    const unsigned offA_w = ((r8 + ((quad & 1) << 3)) * WS_STRIDE + ((quad >> 1) << 3)) * 2;
    const unsigned xs_u = (unsigned)__cvta_generic_to_shared(Xs);
    const unsigned ws_u = (unsigned)__cvta_generic_to_shared(Ws);

    // cp.async chunk maps (16B = 8 halfs per chunk):
    // X stage: 128 rows x 32 halfs = 512 chunks -> 2 per thread, 4 chunks/row
    // W stage: 32 rows x 128 halfs = 512 chunks -> 2 per thread, 16 chunks/row
    int xr_[2], xc_[2], wr_[2], wc_[2];
    #pragma unroll
    for (int i = 0; i < 2; i++) {
        int id = tid + i * 256;                  // 0..511
        xr_[i] = id >> 2;  xc_[i] = (id & 3) << 3;     // rows 0..127
        wr_[i] = id >> 4;  wc_[i] = (id & 15) << 3;    // rows 0..31
    }

    auto issue_stage = [&](int s, int k0) {
        #pragma unroll
        for (int i = 0; i < 2; i++)
            cp16(xs_u + (s * XS_TILE + xr_[i] * XS_STRIDE + xc_[i]) * 2,
                 g_x + (size_t)(m0 + xr_[i]) * E_ + k0 + xc_[i]);
        #pragma unroll
        for (int i = 0; i < 2; i++)
            cp16(ws_u + (s * WS_TILE + wr_[i] * WS_STRIDE + wc_[i]) * 2,
                 W + (size_t)(k0 + wr_[i]) * H_ + wc_[i]);
        asm volatile("cp.async.commit_group;");
    };

    float acc[2][8][4];
    #pragma unroll
    for (int i = 0; i < 2; i++)
        #pragma unroll
        for (int j = 0; j < 8; j++)
            #pragma unroll
            for (int r = 0; r < 4; r++) acc[i][j][r] = 0.f;

    issue_stage(0, 0);
    issue_stage(1, 32);
    issue_stage(2, 64);

    const int NIT = E_ / 32;   // 128
    for (int it = 0; it < NIT; it++) {
        const int st = it & (NSTAGE - 1);
        asm volatile("cp.async.wait_group 2;");
        __syncthreads();

        #pragma unroll
        for (int kb = 0; kb < 2; kb++) {
            unsigned a[2][4];
            #pragma unroll
            for (int mt = 0; mt < 2; mt++)
                ldsm4(a[mt], xs_u + (st * XS_TILE + (wm * 32 + mt * 16) * XS_STRIDE + kb * 16) * 2 + offA_x);
            #pragma unroll
            for (int d2 = 0; d2 < 4; d2++) {
                unsigned bb[4];
                ldsm4t(bb, ws_u + (st * WS_TILE + (kb * 16) * WS_STRIDE + wn * 64 + d2 * 16) * 2 + offA_w);
                #pragma unroll
                for (int mt = 0; mt < 2; mt++) {
                    mma16816(acc[mt][d2 * 2],     a[mt], bb);
                    mma16816(acc[mt][d2 * 2 + 1], a[mt], bb + 2);
                }
            }
        }
        if (it + 3 < NIT)
            issue_stage((it + 3) & (NSTAGE - 1), (it + 3) * 32);
    }

    #pragma unroll
    for (int mt = 0; mt < 2; mt++)
        #pragma unroll
        for (int nt = 0; nt < 8; nt++) {
            int row = m0 + wm * 32 + mt * 16 + g;
            int col = wn * 64 + nt * 8 + t * 2;
            *(__half2*)&C[(size_t)row * H_ + col] =
                __floats2half2_rn(acc[mt][nt][0] * csc, acc[mt][nt][1] * csc);
            *(__half2*)&C[(size_t)(row + 8) * H_ + col] =
                __floats2half2_rn(acc[mt][nt][2] * csc, acc[mt][nt][3] * csc);
        }
}

// ---------------------------------------------------------------------------
// Flash attention (unchanged from R4 pass): 128 q-rows/CTA, online softmax,
// P register-resident, K/V double-buffered cp.async.
// ---------------------------------------------------------------------------
#define FS_STRIDE 136
#define FS_TILE (128 * FS_STRIDE)

__global__ __launch_bounds__(256, 1) void flash_kernel(float* __restrict__ out)
{
    extern __shared__ __half fsm[];
    const unsigned q_u  = (unsigned)__cvta_generic_to_shared(fsm);
    const unsigned k_u0 = q_u + FS_TILE * 2;
    const unsigned k_u1 = q_u + FS_TILE * 4;
    const unsigned v_u0 = q_u + FS_TILE * 6;
    const unsigned v_u1 = q_u + FS_TILE * 8;

    const int b = blockIdx.y;
    const int q0 = blockIdx.x * 128;
    const int tid = threadIdx.x;
    const int warp = tid >> 5, lane = tid & 31;
    const int g = lane >> 2, t = lane & 3;
    const int r8 = lane & 7, quad = lane >> 3;

    const __half* gQ = g_q + ((size_t)b * S_ + q0) * H_;
    const __half* gK = g_k + (size_t)b * S_ * H_;
    const __half* gV = g_v + (size_t)b * S_ * H_;

    const unsigned offA = ((r8 + ((quad & 1) << 3)) * FS_STRIDE + ((quad >> 1) << 3)) * 2;
    const unsigned offB = ((r8 + ((quad >> 1) << 3)) * FS_STRIDE + ((quad & 1) << 3)) * 2;

    int ch_r[8], ch_c[8];
    #pragma unroll
    for (int i = 0; i < 8; i++) {
        int id = tid + i * 256;
        ch_r[i] = id >> 4;
        ch_c[i] = (id & 15) << 3;
    }

    #pragma unroll
    for (int i = 0; i < 8; i++) {
        unsigned so = (ch_r[i] * FS_STRIDE + ch_c[i]) * 2;
        const size_t go = (size_t)ch_r[i] * H_ + ch_c[i];
        cp16(q_u + so,  gQ + go);
        cp16(k_u0 + so, gK + go);
        cp16(v_u0 + so, gV + go);
    }
    asm volatile("cp.async.commit_group;");

    float o[16][4];
    #pragma unroll
    for (int i = 0; i < 16; i++)
        #pragma unroll
        for (int r = 0; r < 4; r++) o[i][r] = 0.f;
    float mr0 = -1e30f, mr1 = -1e30f, l0 = 0.f, l1 = 0.f;

    asm volatile("cp.async.wait_group 0;");
    __syncthreads();

    for (int j = 0; j < S_ / 128; j++) {
        const unsigned kb_u = (j & 1) ? k_u1 : k_u0;
        const unsigned vb_u = (j & 1) ? v_u1 : v_u0;

        if (j + 1 < S_ / 128) {
            const unsigned kn_u = (j & 1) ? k_u0 : k_u1;
            const unsigned vn_u = (j & 1) ? v_u0 : v_u1;
            const __half* srcK = gK + (size_t)(j + 1) * 128 * H_;
            const __half* srcV = gV + (size_t)(j + 1) * 128 * H_;
            #pragma unroll
            for (int i = 0; i < 8; i++) {
                unsigned so = (ch_r[i] * FS_STRIDE + ch_c[i]) * 2;
                const size_t go = (size_t)ch_r[i] * H_ + ch_c[i];
                cp16(kn_u + so, srcK + go);
                cp16(vn_u + so, srcV + go);
            }
            asm volatile("cp.async.commit_group;");
        }

        float s[16][4];
        #pragma unroll
        for (int i = 0; i < 16; i++)
            #pragma unroll
            for (int r = 0; r < 4; r++) s[i][r] = 0.f;

        #pragma unroll
        for (int kb = 0; kb < 8; kb++) {
            unsigned a[4];
            ldsm4(a, q_u + ((warp * 16) * FS_STRIDE + kb * 16) * 2 + offA);
            #pragma unroll
            for (int n2 = 0; n2 < 8; n2++) {
                unsigned bb[4];
                ldsm4(bb, kb_u + ((n2 * 16) * FS_STRIDE + kb * 16) * 2 + offB);
                mma16816(s[n2 * 2],     a, bb);
                mma16816(s[n2 * 2 + 1], a, bb + 2);
            }
        }

        float mx0 = -1e30f, mx1 = -1e30f;
        #pragma unroll
        for (int i = 0; i < 16; i++) {
            mx0 = fmaxf(mx0, fmaxf(s[i][0], s[i][1]));
            mx1 = fmaxf(mx1, fmaxf(s[i][2], s[i][3]));
        }
        mx0 = fmaxf(mx0, __shfl_xor_sync(0xffffffffu, mx0, 1));
        mx0 = fmaxf(mx0, __shfl_xor_sync(0xffffffffu, mx0, 2));
        mx1 = fmaxf(mx1, __shfl_xor_sync(0xffffffffu, mx1, 1));
        mx1 = fmaxf(mx1, __shfl_xor_sync(0xffffffffu, mx1, 2));

        const float mn0 = fmaxf(mr0, mx0), mn1 = fmaxf(mr1, mx1);
        const float cor0 = ex2(mr0 - mn0), cor1 = ex2(mr1 - mn1);
        mr0 = mn0; mr1 = mn1;
        l0 *= cor0; l1 *= cor1;
        #pragma unroll
        for (int i = 0; i < 16; i++) {
            o[i][0] *= cor0; o[i][1] *= cor0;
            o[i][2] *= cor1; o[i][3] *= cor1;
        }

        unsigned p[8][4];
        float s0 = 0.f, s1 = 0.f;
        #pragma unroll
        for (int n2 = 0; n2 < 8; n2++) {
            float e0 = ex2(s[2 * n2][0] - mn0), e1 = ex2(s[2 * n2][1] - mn0);
            float e2 = ex2(s[2 * n2][2] - mn1), e3 = ex2(s[2 * n2][3] - mn1);
            float f0 = ex2(s[2 * n2 + 1][0] - mn0), f1 = ex2(s[2 * n2 + 1][1] - mn0);
            float f2 = ex2(s[2 * n2 + 1][2] - mn1), f3 = ex2(s[2 * n2 + 1][3] - mn1);
            s0 += e0 + e1 + f0 + f1;
            s1 += e2 + e3 + f2 + f3;
            p[n2][0] = packh2(e0, e1);
            p[n2][1] = packh2(e2, e3);
            p[n2][2] = packh2(f0, f1);
            p[n2][3] = packh2(f2, f3);
        }
        l0 += s0; l1 += s1;

        #pragma unroll
        for (int kb = 0; kb < 8; kb++) {
            #pragma unroll
            for (int d2 = 0; d2 < 8; d2++) {
                unsigned bb[4];
                ldsm4t(bb, vb_u + ((kb * 16) * FS_STRIDE + d2 * 16) * 2 + offA);
                mma16816(o[d2 * 2],     p[kb], bb);
                mma16816(o[d2 * 2 + 1], p[kb], bb + 2);
            }
        }

        asm volatile("cp.async.wait_group 0;");
        __syncthreads();
    }

    l0 += __shfl_xor_sync(0xffffffffu, l0, 1);
    l0 += __shfl_xor_sync(0xffffffffu, l0, 2);
    l1 += __shfl_xor_sync(0xffffffffu, l1, 1);
    l1 += __shfl_xor_sync(0xffffffffu, l1, 2);
    const float inv0 = 1.f / l0, inv1 = 1.f / l1;

    const size_t row0 = (size_t)b * S_ + q0 + warp * 16 + g;
    #pragma unroll
    for (int nt = 0; nt < 16; nt++) {
        int col = nt * 8 + t * 2;
        *(float2*)&out[row0 * H_ + col] =
            make_float2(o[nt][0] * inv0, o[nt][1] * inv0);
        *(float2*)&out[(row0 + 8) * H_ + col] =
            make_float2(o[nt][2] * inv1, o[nt][3] * inv1);
    }
}

// ---------------------------------------------------------------------------
extern "C" void kernel_launch(void* const* d_in, const int* in_sizes, int n_in,
                              void* d_out, int out_size)
{
    const float* x  = (const float*)d_in[0];
    const float* Wq = (const float*)d_in[1];
    const float* Wk = (const float*)d_in[2];
    const float* Wv = (const float*)d_in[3];
    float* out = (float*)d_out;
    (void)in_sizes; (void)n_in; (void)out_size;

    const int flash_smem = 5 * FS_TILE * 2;   // 174080 B

    cudaFuncSetAttribute(proj_fp16,
                         cudaFuncAttributeMaxDynamicSharedMemorySize, PROJ_SMEM);
    cudaFuncSetAttribute(flash_kernel,
                         cudaFuncAttributeMaxDynamicSharedMemorySize, flash_smem);

    // x: 67,108,864 floats / 8 per thread / 256 per block = 32768 blocks
    cvt_x_kernel<<<32768, 256>>>(x);
    // each W: 524,288 floats / 8 / 256 = 256 blocks
    cvt_w_kernel<<<dim3(256, 3), 256>>>(Wq, Wk, Wv);

    proj_fp16<<<dim3(128, 1, 3), 256, PROJ_SMEM>>>();
    flash_kernel<<<dim3(S_ / 128, B_), 256, flash_smem>>>(out);
}

// round 11
// speedup vs baseline: 7.6250x; 1.6103x over previous
#include <cuda_runtime.h>
#include <cuda_fp16.h>

#define B_ 8
#define S_ 2048
#define E_ 4096
#define H_ 128

__device__ __align__(16) __half g_wq[E_ * H_];
__device__ __align__(16) __half g_wk[E_ * H_];
__device__ __align__(16) __half g_wv[E_ * H_];
__device__ __align__(16) __half g_q[B_ * S_ * H_];
__device__ __align__(16) __half g_k[B_ * S_ * H_];
__device__ __align__(16) __half g_v[B_ * S_ * H_];

// ---------------------------------------------------------------------------
__device__ __forceinline__ void ldsm4(unsigned* r, unsigned addr) {
    asm volatile("ldmatrix.sync.aligned.m8n8.x4.shared.b16 {%0,%1,%2,%3}, [%4];"
                 : "=r"(r[0]), "=r"(r[1]), "=r"(r[2]), "=r"(r[3]) : "r"(addr));
}
__device__ __forceinline__ void ldsm4t(unsigned* r, unsigned addr) {
    asm volatile("ldmatrix.sync.aligned.m8n8.x4.trans.shared.b16 {%0,%1,%2,%3}, [%4];"
                 : "=r"(r[0]), "=r"(r[1]), "=r"(r[2]), "=r"(r[3]) : "r"(addr));
}
__device__ __forceinline__ void mma16816(float* d, const unsigned* a, const unsigned* b) {
    asm volatile(
        "mma.sync.aligned.m16n8k16.row.col.f32.f16.f16.f32 "
        "{%0,%1,%2,%3}, {%4,%5,%6,%7}, {%8,%9}, {%0,%1,%2,%3};"
        : "+f"(d[0]), "+f"(d[1]), "+f"(d[2]), "+f"(d[3])
        : "r"(a[0]), "r"(a[1]), "r"(a[2]), "r"(a[3]), "r"(b[0]), "r"(b[1]));
}
__device__ __forceinline__ void cp16(unsigned dst, const void* src) {
    asm volatile("cp.async.cg.shared.global [%0], [%1], 16;" :: "r"(dst), "l"(src));
}
__device__ __forceinline__ float ex2(float x) {
    float y; asm("ex2.approx.ftz.f32 %0, %1;" : "=f"(y) : "f"(x)); return y;
}
__device__ __forceinline__ unsigned packh2(float a, float b) {
    __half2 h = __floats2half2_rn(a, b);
    return *(unsigned*)&h;
}

// ---------------------------------------------------------------------------
// W converters fp32->fp16 (6 MB total; ~3 us)
// ---------------------------------------------------------------------------
__global__ __launch_bounds__(256) void cvt_w_kernel(
    const float* __restrict__ Wq, const float* __restrict__ Wk,
    const float* __restrict__ Wv)
{
    const int z = blockIdx.y;
    const float* src = (z == 0) ? Wq : (z == 1) ? Wk : Wv;
    __half* dst      = (z == 0) ? g_wq : (z == 1) ? g_wk : g_wv;
    const size_t i = ((size_t)blockIdx.x * 256 + threadIdx.x) * 8;
    float4 a = *(const float4*)(src + i);
    float4 b = *(const float4*)(src + i + 4);
    uint4 u;
    u.x = packh2(a.x, a.y); u.y = packh2(a.z, a.w);
    u.z = packh2(b.x, b.y); u.w = packh2(b.z, b.w);
    *(uint4*)(dst + i) = u;
}

// ---------------------------------------------------------------------------
// Fused QKV projection: {q,k,v}[16384,128] = x[16384,4096] @ {Wq,Wk,Wv}
// x read fp32 ONCE; in-pipeline fp16 convert; A-fragments shared by 3 B's.
// BM=128, BK=32, 3-stage cp.async (one commit EVERY iteration -> tail-safe).
// ---------------------------------------------------------------------------
#define NST 3
#define X32_STRIDE 36
#define X32_TILE (128 * X32_STRIDE)
#define XS_STRIDE 40
#define XS_TILE (128 * XS_STRIDE)
#define WS_STRIDE 136
#define WS_TILE (32 * WS_STRIDE)

#define X32_OFF 0
#define XSH_OFF (NST * X32_TILE * 4)
#define WS_OFF  (XSH_OFF + NST * XS_TILE * 2)
#define QKV_SMEM (WS_OFF + 3 * NST * WS_TILE * 2)   // 164352 B

__global__ __launch_bounds__(256, 1) void qkv_fused(const float* __restrict__ x)
{
    extern __shared__ char qsm[];
    float*  Xs32 = (float*)(qsm + X32_OFF);
    __half* Xsh  = (__half*)(qsm + XSH_OFF);
    __half* Ws   = (__half*)(qsm + WS_OFF);

    const int m0   = blockIdx.x * 128;
    const int tid  = threadIdx.x;
    const int warp = tid >> 5, lane = tid & 31;
    const int wm = warp >> 1, wn = warp & 1;
    const int g = lane >> 2, t = lane & 3;
    const int r8 = lane & 7, quad = lane >> 3;

    const __half* Wg[3] = { g_wq, g_wk, g_wv };
    __half* Cg[3]       = { g_q, g_k, g_v };

    const unsigned offA_x = ((r8 + ((quad & 1) << 3)) * XS_STRIDE + ((quad >> 1) << 3)) * 2;
    const unsigned offB_w = ((r8 + ((quad & 1) << 3)) * WS_STRIDE + ((quad >> 1) << 3)) * 2;
    const unsigned x32_u = (unsigned)__cvta_generic_to_shared(Xs32);
    const unsigned xsh_u = (unsigned)__cvta_generic_to_shared(Xsh);
    const unsigned ws_u  = (unsigned)__cvta_generic_to_shared(Ws);

    // X fp32 stage: 128 rows x 32 floats = 1024 16B-chunks; 4/thread
    int xr_[4], xc_[4];
    #pragma unroll
    for (int i = 0; i < 4; i++) {
        int id = tid + i * 256;
        xr_[i] = id >> 3;
        xc_[i] = (id & 7) << 2;
    }
    // W stage per matrix: 32 rows x 128 halfs = 512 chunks; 2/thread
    int wr_[2], wc_[2];
    #pragma unroll
    for (int i = 0; i < 2; i++) {
        int id = tid + i * 256;
        wr_[i] = id >> 4;
        wc_[i] = (id & 15) << 3;
    }

    // NOTE: no commit inside -- caller commits exactly once per pipeline slot.
    auto issue_stage = [&](int s, int k0) {
        #pragma unroll
        for (int i = 0; i < 4; i++)
            cp16(x32_u + (s * X32_TILE + xr_[i] * X32_STRIDE + xc_[i]) * 4,
                 x + (size_t)(m0 + xr_[i]) * E_ + k0 + xc_[i]);
        #pragma unroll
        for (int z = 0; z < 3; z++)
            #pragma unroll
            for (int i = 0; i < 2; i++)
                cp16(ws_u + ((z * NST + s) * WS_TILE + wr_[i] * WS_STRIDE + wc_[i]) * 2,
                     Wg[z] + (size_t)(k0 + wr_[i]) * H_ + wc_[i]);
    };

    const int cv_row = tid >> 1;
    const int cv_col = (tid & 1) << 4;
    auto convert_stage = [&](int s) {
        const float* src = Xs32 + s * X32_TILE + cv_row * X32_STRIDE + cv_col;
        __half* dst = Xsh + s * XS_TILE + cv_row * XS_STRIDE + cv_col;
        float4 a0 = *(const float4*)(src);
        float4 a1 = *(const float4*)(src + 4);
        float4 a2 = *(const float4*)(src + 8);
        float4 a3 = *(const float4*)(src + 12);
        uint4 u0, u1;
        u0.x = packh2(a0.x, a0.y); u0.y = packh2(a0.z, a0.w);
        u0.z = packh2(a1.x, a1.y); u0.w = packh2(a1.z, a1.w);
        u1.x = packh2(a2.x, a2.y); u1.y = packh2(a2.z, a2.w);
        u1.z = packh2(a3.x, a3.y); u1.w = packh2(a3.z, a3.w);
        *(uint4*)(dst)     = u0;
        *(uint4*)(dst + 8) = u1;
    };

    float acc[3][2][8][4];
    #pragma unroll
    for (int z = 0; z < 3; z++)
        #pragma unroll
        for (int i = 0; i < 2; i++)
            #pragma unroll
            for (int j = 0; j < 8; j++)
                #pragma unroll
                for (int r = 0; r < 4; r++) acc[z][i][j][r] = 0.f;

    issue_stage(0, 0);
    asm volatile("cp.async.commit_group;");
    issue_stage(1, 32);
    asm volatile("cp.async.commit_group;");

    const int NIT = E_ / 32;   // 128
    for (int it = 0; it < NIT; it++) {
        const int st = it % NST;
        asm volatile("cp.async.wait_group 1;");
        __syncthreads();
        convert_stage(st);
        __syncthreads();

        #pragma unroll
        for (int kb = 0; kb < 2; kb++) {
            unsigned a[2][4];
            #pragma unroll
            for (int mt = 0; mt < 2; mt++)
                ldsm4(a[mt], xsh_u + (st * XS_TILE + (wm * 32 + mt * 16) * XS_STRIDE + kb * 16) * 2 + offA_x);
            #pragma unroll
            for (int z = 0; z < 3; z++)
                #pragma unroll
                for (int d2 = 0; d2 < 4; d2++) {
                    unsigned bb[4];
                    ldsm4t(bb, ws_u + ((z * NST + st) * WS_TILE + (kb * 16) * WS_STRIDE + wn * 64 + d2 * 16) * 2 + offB_w);
                    #pragma unroll
                    for (int mt = 0; mt < 2; mt++) {
                        mma16816(acc[z][mt][d2 * 2],     a[mt], bb);
                        mma16816(acc[z][mt][d2 * 2 + 1], a[mt], bb + 2);
                    }
                }
        }
        // commit EVERY iteration (empty groups in the tail keep wait_group
        // accounting exact -- the group for slot it%NST is always drained).
        if (it + 2 < NIT)
            issue_stage((it + 2) % NST, (it + 2) * 32);
        asm volatile("cp.async.commit_group;");
    }

    const float qsc = (float)(0.08838834764831845 * 1.4426950408889634);
    #pragma unroll
    for (int z = 0; z < 3; z++) {
        const float csc = (z == 0) ? qsc : 1.0f;
        __half* C = Cg[z];
        #pragma unroll
        for (int mt = 0; mt < 2; mt++)
            #pragma unroll
            for (int nt = 0; nt < 8; nt++) {
                int row = m0 + wm * 32 + mt * 16 + g;
                int col = wn * 64 + nt * 8 + t * 2;
                *(__half2*)&C[(size_t)row * H_ + col] =
                    __floats2half2_rn(acc[z][mt][nt][0] * csc, acc[z][mt][nt][1] * csc);
                *(__half2*)&C[(size_t)(row + 8) * H_ + col] =
                    __floats2half2_rn(acc[z][mt][nt][2] * csc, acc[z][mt][nt][3] * csc);
            }
    }
}

// ---------------------------------------------------------------------------
// Flash attention (unchanged, proven; wait_group 0 = tail-safe by design).
// ---------------------------------------------------------------------------
#define FS_STRIDE 136
#define FS_TILE (128 * FS_STRIDE)

__global__ __launch_bounds__(256, 1) void flash_kernel(float* __restrict__ out)
{
    extern __shared__ __half fsm[];
    const unsigned q_u  = (unsigned)__cvta_generic_to_shared(fsm);
    const unsigned k_u0 = q_u + FS_TILE * 2;
    const unsigned k_u1 = q_u + FS_TILE * 4;
    const unsigned v_u0 = q_u + FS_TILE * 6;
    const unsigned v_u1 = q_u + FS_TILE * 8;

    const int b = blockIdx.y;
    const int q0 = blockIdx.x * 128;
    const int tid = threadIdx.x;
    const int warp = tid >> 5, lane = tid & 31;
    const int g = lane >> 2, t = lane & 3;
    const int r8 = lane & 7, quad = lane >> 3;

    const __half* gQ = g_q + ((size_t)b * S_ + q0) * H_;
    const __half* gK = g_k + (size_t)b * S_ * H_;
    const __half* gV = g_v + (size_t)b * S_ * H_;

    const unsigned offA = ((r8 + ((quad & 1) << 3)) * FS_STRIDE + ((quad >> 1) << 3)) * 2;
    const unsigned offB = ((r8 + ((quad >> 1) << 3)) * FS_STRIDE + ((quad & 1) << 3)) * 2;

    int ch_r[8], ch_c[8];
    #pragma unroll
    for (int i = 0; i < 8; i++) {
        int id = tid + i * 256;
        ch_r[i] = id >> 4;
        ch_c[i] = (id & 15) << 3;
    }

    #pragma unroll
    for (int i = 0; i < 8; i++) {
        unsigned so = (ch_r[i] * FS_STRIDE + ch_c[i]) * 2;
        const size_t go = (size_t)ch_r[i] * H_ + ch_c[i];
        cp16(q_u + so,  gQ + go);
        cp16(k_u0 + so, gK + go);
        cp16(v_u0 + so, gV + go);
    }
    asm volatile("cp.async.commit_group;");

    float o[16][4];
    #pragma unroll
    for (int i = 0; i < 16; i++)
        #pragma unroll
        for (int r = 0; r < 4; r++) o[i][r] = 0.f;
    float mr0 = -1e30f, mr1 = -1e30f, l0 = 0.f, l1 = 0.f;

    asm volatile("cp.async.wait_group 0;");
    __syncthreads();

    for (int j = 0; j < S_ / 128; j++) {
        const unsigned kb_u = (j & 1) ? k_u1 : k_u0;
        const unsigned vb_u = (j & 1) ? v_u1 : v_u0;

        if (j + 1 < S_ / 128) {
            const unsigned kn_u = (j & 1) ? k_u0 : k_u1;
            const unsigned vn_u = (j & 1) ? v_u0 : v_u1;
            const __half* srcK = gK + (size_t)(j + 1) * 128 * H_;
            const __half* srcV = gV + (size_t)(j + 1) * 128 * H_;
            #pragma unroll
            for (int i = 0; i < 8; i++) {
                unsigned so = (ch_r[i] * FS_STRIDE + ch_c[i]) * 2;
                const size_t go = (size_t)ch_r[i] * H_ + ch_c[i];
                cp16(kn_u + so, srcK + go);
                cp16(vn_u + so, srcV + go);
            }
        }
        asm volatile("cp.async.commit_group;");

        float s[16][4];
        #pragma unroll
        for (int i = 0; i < 16; i++)
            #pragma unroll
            for (int r = 0; r < 4; r++) s[i][r] = 0.f;

        #pragma unroll
        for (int kb = 0; kb < 8; kb++) {
            unsigned a[4];
            ldsm4(a, q_u + ((warp * 16) * FS_STRIDE + kb * 16) * 2 + offA);
            #pragma unroll
            for (int n2 = 0; n2 < 8; n2++) {
                unsigned bb[4];
                ldsm4(bb, kb_u + ((n2 * 16) * FS_STRIDE + kb * 16) * 2 + offB);
                mma16816(s[n2 * 2],     a, bb);
                mma16816(s[n2 * 2 + 1], a, bb + 2);
            }
        }

        float mx0 = -1e30f, mx1 = -1e30f;
        #pragma unroll
        for (int i = 0; i < 16; i++) {
            mx0 = fmaxf(mx0, fmaxf(s[i][0], s[i][1]));
            mx1 = fmaxf(mx1, fmaxf(s[i][2], s[i][3]));
        }
        mx0 = fmaxf(mx0, __shfl_xor_sync(0xffffffffu, mx0, 1));
        mx0 = fmaxf(mx0, __shfl_xor_sync(0xffffffffu, mx0, 2));
        mx1 = fmaxf(mx1, __shfl_xor_sync(0xffffffffu, mx1, 1));
        mx1 = fmaxf(mx1, __shfl_xor_sync(0xffffffffu, mx1, 2));

        const float mn0 = fmaxf(mr0, mx0), mn1 = fmaxf(mr1, mx1);
        const float cor0 = ex2(mr0 - mn0), cor1 = ex2(mr1 - mn1);
        mr0 = mn0; mr1 = mn1;
        l0 *= cor0; l1 *= cor1;
        #pragma unroll
        for (int i = 0; i < 16; i++) {
            o[i][0] *= cor0; o[i][1] *= cor0;
            o[i][2] *= cor1; o[i][3] *= cor1;
        }

        unsigned p[8][4];
        float s0 = 0.f, s1 = 0.f;
        #pragma unroll
        for (int n2 = 0; n2 < 8; n2++) {
            float e0 = ex2(s[2 * n2][0] - mn0), e1 = ex2(s[2 * n2][1] - mn0);
            float e2 = ex2(s[2 * n2][2] - mn1), e3 = ex2(s[2 * n2][3] - mn1);
            float f0 = ex2(s[2 * n2 + 1][0] - mn0), f1 = ex2(s[2 * n2 + 1][1] - mn0);
            float f2 = ex2(s[2 * n2 + 1][2] - mn1), f3 = ex2(s[2 * n2 + 1][3] - mn1);
            s0 += e0 + e1 + f0 + f1;
            s1 += e2 + e3 + f2 + f3;
            p[n2][0] = packh2(e0, e1);
            p[n2][1] = packh2(e2, e3);
            p[n2][2] = packh2(f0, f1);
            p[n2][3] = packh2(f2, f3);
        }
        l0 += s0; l1 += s1;

        #pragma unroll
        for (int kb = 0; kb < 8; kb++) {
            #pragma unroll
            for (int d2 = 0; d2 < 8; d2++) {
                unsigned bb[4];
                ldsm4t(bb, vb_u + ((kb * 16) * FS_STRIDE + d2 * 16) * 2 + offA);
                mma16816(o[d2 * 2],     p[kb], bb);
                mma16816(o[d2 * 2 + 1], p[kb], bb + 2);
            }
        }

        asm volatile("cp.async.wait_group 0;");
        __syncthreads();
    }

    l0 += __shfl_xor_sync(0xffffffffu, l0, 1);
    l0 += __shfl_xor_sync(0xffffffffu, l0, 2);
    l1 += __shfl_xor_sync(0xffffffffu, l1, 1);
    l1 += __shfl_xor_sync(0xffffffffu, l1, 2);
    const float inv0 = 1.f / l0, inv1 = 1.f / l1;

    const size_t row0 = (size_t)b * S_ + q0 + warp * 16 + g;
    #pragma unroll
    for (int nt = 0; nt < 16; nt++) {
        int col = nt * 8 + t * 2;
        *(float2*)&out[row0 * H_ + col] =
            make_float2(o[nt][0] * inv0, o[nt][1] * inv0);
        *(float2*)&out[(row0 + 8) * H_ + col] =
            make_float2(o[nt][2] * inv1, o[nt][3] * inv1);
    }
}

// ---------------------------------------------------------------------------
extern "C" void kernel_launch(void* const* d_in, const int* in_sizes, int n_in,
                              void* d_out, int out_size)
{
    const float* x  = (const float*)d_in[0];
    const float* Wq = (const float*)d_in[1];
    const float* Wk = (const float*)d_in[2];
    const float* Wv = (const float*)d_in[3];
    float* out = (float*)d_out;
    (void)in_sizes; (void)n_in; (void)out_size;

    const int flash_smem = 5 * FS_TILE * 2;   // 174080 B

    cudaFuncSetAttribute(qkv_fused,
                         cudaFuncAttributeMaxDynamicSharedMemorySize, QKV_SMEM);
    cudaFuncSetAttribute(flash_kernel,
                         cudaFuncAttributeMaxDynamicSharedMemorySize, flash_smem);

    cvt_w_kernel<<<dim3(256, 3), 256>>>(Wq, Wk, Wv);
    qkv_fused<<<dim3(S_ * B_ / 128), 256, QKV_SMEM>>>(x);
    flash_kernel<<<dim3(S_ / 128, B_), 256, flash_smem>>>(out);
}